// round 7
// baseline (speedup 1.0000x reference)
#include <cuda_runtime.h>
#include <cstdint>

// Problem dims (fixed by dataset)
#define BB 8
#define CC 96
#define GG 64   // PY*PX = 8*8
#define JJ 17
#define KK 96
#define NTHR 256
#define NWARPS (NTHR/32)
#define GSTRIDE 68            // padded row stride (floats), 272B: 16B-aligned rows
#define WIDTH_F 128.0f
#define LOG2E 1.4426950408889634f

// Output layout: concat(oks_parts_sel [B,C,G,J], oks_person_sel [B,C,G], pose_gt [B,C,J,3])
#define PARTS_SZ  (BB*CC*GG*JJ)
#define PERSON_SZ (BB*CC*GG)
#define PERSON_OFF PARTS_SZ
#define POSE_OFF  (PARTS_SZ + PERSON_SZ)

typedef unsigned long long u64;

__device__ __forceinline__ float fast_ex2(float x) {
    float y;
    asm("ex2.approx.ftz.f32 %0, %1;" : "=f"(y) : "f"(x));
    return y;
}
__device__ __forceinline__ u64 pack_f32x2(float lo, float hi) {
    u64 r; asm("mov.b64 %0, {%1, %2};" : "=l"(r) : "f"(lo), "f"(hi)); return r;
}
__device__ __forceinline__ u64 add_f32x2(u64 a, u64 b) {
    u64 r; asm("add.rn.f32x2 %0, %1, %2;" : "=l"(r) : "l"(a), "l"(b)); return r;
}
__device__ __forceinline__ u64 mul_f32x2(u64 a, u64 b) {
    u64 r; asm("mul.rn.f32x2 %0, %1, %2;" : "=l"(r) : "l"(a), "l"(b)); return r;
}
__device__ __forceinline__ u64 fma_f32x2(u64 a, u64 b, u64 c) {
    u64 r; asm("fma.rn.f32x2 %0, %1, %2, %3;" : "=l"(r) : "l"(a), "l"(b), "l"(c)); return r;
}
__device__ __forceinline__ float2 unpack_f32x2(u64 v) {
    float2 f; asm("mov.b64 {%0, %1}, %2;" : "=f"(f.x), "=f"(f.y) : "l"(v)); return f;
}

__global__ __launch_bounds__(NTHR, 5)
void oks_assign_kernel(
    const float* __restrict__ pose_pool,   // [B,C,8,8,J,2]
    const float* __restrict__ keypoints,   // [B,K,J,3]
    const float* __restrict__ areas,       // [B,K]
    const float* __restrict__ transforms,  // [B,3,3]
    const float* __restrict__ tinv,        // [B,3,3]
    const int*   __restrict__ hflip,       // [B]
    const float* __restrict__ sigmas,      // [J]
    float* __restrict__ out)
{
    const int c = blockIdx.x;
    const int b = blockIdx.y;
    const int tid  = threadIdx.x;
    const int wid  = tid >> 5;
    const int lane = tid & 31;

    __shared__ __align__(16) float s_x[JJ * GSTRIDE];
    __shared__ __align__(16) float s_y[JJ * GSTRIDE];
    __shared__ __align__(16) float s_val[KK * JJ];   // phase B result / phase D oks map
    __shared__ float s_score[KK];
    __shared__ float s_ivs[KK];
    __shared__ float s_sig[JJ];
    __shared__ int   s_kstar;

    if (tid < JJ) s_sig[tid] = sigmas[tid];

    const float ti00 = tinv[b*9+0], ti01 = tinv[b*9+1], ti02 = tinv[b*9+2];
    const float ti10 = tinv[b*9+3], ti11 = tinv[b*9+4], ti12 = tinv[b*9+5];
    const bool flip = hflip[b] > 0;

    // ---- Phase A: pool -> image coords into SMEM, x/y split, padded rows ----
    const float2* pp = (const float2*)(pose_pool + (size_t)(b*CC + c) * GG * JJ * 2);
    for (int idx = tid; idx < GG*JJ; idx += NTHR) {
        int g = idx / JJ, j = idx - g*JJ;
        float2 p = pp[idx];
        float fx = flip ? (WIDTH_F - 1.0f - p.x) : p.x;
        s_x[j*GSTRIDE + g] = fx*ti00 + p.y*ti01 + ti02;
        s_y[j*GSTRIDE + g] = fx*ti10 + p.y*ti11 + ti12;
    }

    // ---- vis_sum per k ----
    const float* kpt = keypoints + (size_t)b * KK * JJ * 3;
    for (int k = tid; k < KK; k += NTHR) {
        float vs = 0.f;
        #pragma unroll
        for (int j = 0; j < JJ; j++)
            vs += (kpt[(k*JJ + j)*3 + 2] > 0.f) ? 1.0f : 0.0f;
        s_ivs[k] = 1.0f / fmaxf(vs, 1.0f);
    }
    __syncthreads();

    // ---- Phase B: warp-uniform j, broadcast coord loads, packed f32x2 math ----
    // max_g exp(scale*d2) == exp(scale * min_g d2) (scale<0, ex2 monotone).
    for (int j = wid; j < JJ; j += NWARPS) {
        const float* rowx = s_x + j*GSTRIDE;
        const float* rowy = s_y + j*GSTRIDE;

        u64 nkx[3], nky[3];          // (-kx,-kx), (-ky,-ky) per owned k
        float mdA[3], mdB[3];
        #pragma unroll
        for (int kk = 0; kk < 3; kk++) {
            const int k = kk*32 + lane;
            const float* kp = kpt + (k*JJ + j)*3;
            float kx = kp[0], ky = kp[1];
            nkx[kk] = pack_f32x2(-kx, -kx);
            nky[kk] = pack_f32x2(-ky, -ky);
            mdA[kk] = 3.4e38f; mdB[kk] = 3.4e38f;
        }

        #pragma unroll 4
        for (int i = 0; i < GG/4; i++) {
            // broadcast 16B loads: (x0,x1),(x2,x3) and same for y
            const ulonglong2 xx = *(const ulonglong2*)(rowx + i*4);
            const ulonglong2 yy = *(const ulonglong2*)(rowy + i*4);
            #pragma unroll
            for (int kk = 0; kk < 3; kk++) {
                u64 dxa = add_f32x2(xx.x, nkx[kk]);
                u64 dxb = add_f32x2(xx.y, nkx[kk]);
                u64 dya = add_f32x2(yy.x, nky[kk]);
                u64 dyb = add_f32x2(yy.y, nky[kk]);
                u64 pa = fma_f32x2(dxa, dxa, mul_f32x2(dya, dya));
                u64 pb = fma_f32x2(dxb, dxb, mul_f32x2(dyb, dyb));
                float2 fa = unpack_f32x2(pa);
                float2 fb = unpack_f32x2(pb);
                mdA[kk] = fminf(mdA[kk], fminf(fa.x, fa.y));
                mdB[kk] = fminf(mdB[kk], fminf(fb.x, fb.y));
            }
        }

        const float sg = 2.0f * s_sig[j];
        #pragma unroll
        for (int kk = 0; kk < 3; kk++) {
            const int k = kk*32 + lane;
            float v = kpt[(k*JJ + j)*3 + 2];
            float val = 0.0f;
            if (v > 0.0f) {
                float denom = fmaxf(2.0f * sg * sg * areas[b*KK + k], 1e-6f);
                val = fast_ex2(fminf(mdA[kk], mdB[kk]) * (-LOG2E / denom));
            }
            s_val[k*JJ + j] = val;
        }
    }
    __syncthreads();

    // ---- Phase B2: per-k score (deterministic order) ----
    for (int k = tid; k < KK; k += NTHR) {
        float s = 0.f;
        #pragma unroll
        for (int j = 0; j < JJ; j++) s += s_val[k*JJ + j];
        s_score[k] = s * s_ivs[k];
    }
    __syncthreads();

    // ---- Phase C: warp-parallel argmax (first-max semantics) ----
    if (tid < 32) {
        float bs = -1.0f; int bi = 0;
        #pragma unroll
        for (int p = 0; p < KK/32; p++) {
            int k = tid + p*32;                 // ascending k within lane
            float sc = s_score[k];
            if (sc > bs) { bs = sc; bi = k; }   // strictly greater keeps smallest k
        }
        #pragma unroll
        for (int off = 16; off > 0; off >>= 1) {
            float os = __shfl_xor_sync(0xffffffffu, bs, off);
            int   oi = __shfl_xor_sync(0xffffffffu, bi, off);
            if (os > bs || (os == bs && oi < bi)) { bs = os; bi = oi; }
        }
        if (tid == 0) s_kstar = bi;
    }
    __syncthreads();
    const int ks = s_kstar;
    const float area_ks = areas[b*KK + ks];

    // ---- Phase D: OKS map for k* into s_val[g][j] ----
    for (int item = tid; item < GG*JJ; item += NTHR) {
        int j = item / GG, g = item - j*GG;
        float kx = kpt[(ks*JJ + j)*3 + 0];
        float ky = kpt[(ks*JJ + j)*3 + 1];
        float v  = kpt[(ks*JJ + j)*3 + 2];
        float o = 0.0f;
        if (v > 0.0f) {
            float sg = 2.0f * s_sig[j];
            float denom = fmaxf(2.0f * sg * sg * area_ks, 1e-6f);
            float scale = -LOG2E / denom;
            float dx = s_x[j*GSTRIDE + g] - kx;
            float dy = s_y[j*GSTRIDE + g] - ky;
            o = fast_ex2(fmaf(dx, dx, dy*dy) * scale);
        }
        s_val[g*JJ + j] = o;
    }
    __syncthreads();

    // ---- Phase E: emit outputs ----
    {
        float4* parts4 = (float4*)(out + (size_t)(b*CC + c) * GG * JJ);
        const float4* sv4 = (const float4*)s_val;
        for (int idx = tid; idx < (GG*JJ)/4; idx += NTHR) parts4[idx] = sv4[idx];
    }

    float* person = out + PERSON_OFF + (size_t)(b*CC + c) * GG;
    const float ivs_ks = s_ivs[ks];
    for (int g = tid; g < GG; g += NTHR) {
        float s = 0.f;
        #pragma unroll
        for (int j = 0; j < JJ; j++) s += s_val[g*JJ + j];
        person[g] = s * ivs_ks;
    }

    if (tid < JJ) {
        int j = tid;
        float X = kpt[(ks*JJ + j)*3 + 0];
        float Y = kpt[(ks*JJ + j)*3 + 1];
        float V = kpt[(ks*JJ + j)*3 + 2];
        float t00 = transforms[b*9+0], t01 = transforms[b*9+1], t02 = transforms[b*9+2];
        float t10 = transforms[b*9+3], t11 = transforms[b*9+4], t12 = transforms[b*9+5];
        float gx = t00*X + t01*Y + t02;
        float gy = t10*X + t11*Y + t12;
        if (flip) gx = WIDTH_F - 1.0f - gx;
        float sg = 2.0f * s_sig[j];
        float gv = (V > 0.f) ? (t00 * t11) * (area_ks * sg * sg) : 0.0f;
        float* pg = out + POSE_OFF + (size_t)((b*CC + c)*JJ + j) * 3;
        pg[0] = gx; pg[1] = gy; pg[2] = gv;
    }
}

extern "C" void kernel_launch(void* const* d_in, const int* in_sizes, int n_in,
                              void* d_out, int out_size) {
    const float* pose_pool  = (const float*)d_in[0];
    const float* keypoints  = (const float*)d_in[1];
    const float* areas      = (const float*)d_in[2];
    const float* transforms = (const float*)d_in[3];
    const float* tinv       = (const float*)d_in[4];
    const int*   hflip      = (const int*)  d_in[5];
    const float* sigmas     = (const float*)d_in[6];
    float* out = (float*)d_out;

    dim3 grid(CC, BB);
    oks_assign_kernel<<<grid, NTHR>>>(pose_pool, keypoints, areas, transforms,
                                      tinv, hflip, sigmas, out);
}